// round 4
// baseline (speedup 1.0000x reference)
#include <cuda_runtime.h>
#include <cstdint>

// Problem constants
#define NB    32
#define CIN   64
#define COUT  128
#define HDIM  128
#define WDIM  128
#define KK    3
#define NGRP  8
#define EPS   1e-5f

// Fragment-ordered weights: [kh][icc][kw][ks][wn][lane][16], tf32-rounded bits
// total = 3*4*3*2*2*32*16 = 73728 floats
__device__ float g_wt[73728];

// ---------------------------------------------------------------------------
// Weight transform: w (Cin, Cout, 3, 3) -> fragment-ordered tf32 layout.
// Element d decomposes as [kh][icc][kw][ks][wn][lane][e]:
//   e=nt*2+idx, lane=g*4+t; value = w[ic= icc*16+ks*8+t+idx*4][oc= wn*64+nt*8+g][kh][kw]
// ---------------------------------------------------------------------------
__global__ void wt_transform_kernel(const float* __restrict__ w) {
    int d = blockIdx.x * blockDim.x + threadIdx.x;
    if (d >= 73728) return;
    int e    = d & 15;
    int lane = (d >> 4) & 31;
    int wn   = (d >> 9) & 1;
    int ks   = (d >> 10) & 1;
    int r    = d >> 11;
    int kw   = r % 3;
    int hi   = r / 3;
    int icc  = hi & 3;
    int kh   = hi >> 2;
    int nt   = e >> 1;
    int idx2 = e & 1;
    int g    = lane >> 2;
    int t    = lane & 3;
    int ic   = icc * 16 + ks * 8 + t + idx2 * 4;
    int oc   = wn * 64 + nt * 8 + g;
    float v = w[((ic * COUT + oc) * KK + kh) * KK + kw];
    uint32_t rb;
    asm("cvt.rna.tf32.f32 %0, %1;" : "=r"(rb) : "f"(v));
    g_wt[d] = __uint_as_float(rb);
}

// ---------------------------------------------------------------------------
// Helpers
// ---------------------------------------------------------------------------
__device__ __forceinline__ uint32_t f2tf32(float f) {
    uint32_t r;
    asm("cvt.rna.tf32.f32 %0, %1;" : "=r"(r) : "f"(f));
    return r;
}

__device__ __forceinline__ void cp_async16(uint32_t saddr, const void* gaddr, bool pred) {
    int sz = pred ? 16 : 0;  // src-size 0 => zero-fill (ZFILL)
    asm volatile("cp.async.cg.shared.global [%0], [%1], 16, %2;\n"
                 :: "r"(saddr), "l"(gaddr), "r"(sz));
}

// tanh-GELU, zero MUFU: gelu(y) = y * sigmoid(z), z = 2*0.7978845608*(y + 0.044715 y^3)
// exp(-z) = 2^v, v = -z*log2(e) = y*(-2.3022083 - 0.10294832*y^2)
__device__ __forceinline__ float gelu_fast(float y) {
    float y2 = y * y;
    float v  = y * fmaf(-0.10294832f, y2, -2.3022083f);
    v = fminf(fmaxf(v, -126.0f), 126.0f);
    float r = v + 12582912.0f;               // 1.5*2^23: round-to-nearest-int
    float f = v - (r - 12582912.0f);         // f in [-0.5, 0.5]
    int  ri = __float_as_int(r);
    float p = fmaf(f, 0.0096181291f, 0.0555041087f);
    p = fmaf(f, p, 0.2402265069f);
    p = fmaf(f, p, 0.6931471806f);
    p = fmaf(f, p, 1.0f);
    float w = __int_as_float(__float_as_int(p) + (ri << 23));  // 2^v = exp(-z)
    float s = 1.0f + w;
    float x = __int_as_float(0x7EF311C3u - (uint32_t)__float_as_int(s));
    x = x * (2.0f - s * x);
    x = x * (2.0f - s * x);                  // x ~= 1/s, rel err ~3e-6
    return y * x;
}

__device__ __forceinline__ void mma_tf32(float& d0, float& d1, float& d2, float& d3,
                                         uint32_t a0, uint32_t a1, uint32_t a2, uint32_t a3,
                                         uint32_t b0, uint32_t b1) {
    asm volatile(
        "mma.sync.aligned.m16n8k8.row.col.f32.tf32.tf32.f32 "
        "{%0,%1,%2,%3}, {%4,%5,%6,%7}, {%8,%9}, {%0,%1,%2,%3};\n"
        : "+f"(d0), "+f"(d1), "+f"(d2), "+f"(d3)
        : "r"(a0), "r"(a1), "r"(a2), "r"(a3), "r"(b0), "r"(b1));
}

// Shared memory layout (floats), per buffer:
//   Xs: 2 rows-sets x 16 ic x 136  (x data at j=4..131, zeros at j=0..3)
//   Wf: fragment-ordered weights: 3kw x 2ks x 2wn x 32lane x 20 (16 used, pad 4)
#define XROW       136
#define XS_FLOATS  (2 * 16 * XROW)            // 4352
#define WROWF      20
#define WS_FLOATS  (3 * 2 * 2 * 32 * WROWF)   // 7680
#define STAGE_FLOATS (XS_FLOATS + WS_FLOATS)  // 12032
#define SMEM_BYTES (2 * STAGE_FLOATS * 4)     // 96256

// ---------------------------------------------------------------------------
// Fused conv-transpose (cropped) + GELU + per-pixel GroupNorm
// CTA: 2 pixel rows (M=256) x 128 channels, 8 warps (4 m x 2 n), warp 64x64
// ---------------------------------------------------------------------------
__global__ void __launch_bounds__(256, 1)
fused_kernel(const float* __restrict__ x,
             const float* __restrict__ bias,
             const float* __restrict__ gamma,
             const float* __restrict__ beta,
             float* __restrict__ out) {
    extern __shared__ float smem[];
    const int tid  = threadIdx.x;
    const int nimg = blockIdx.y;
    const int r0   = blockIdx.x * 2;

    const uint32_t smem_u = (uint32_t)__cvta_generic_to_shared(smem);

    // Zero the left-pad columns (j=0..3) of Xs in both buffers.
    {
        int b   = tid >> 7;
        int rem = tid & 127;
        int prs = rem >> 6;
        int pi  = (rem >> 2) & 15;
        int pj  = rem & 3;
        smem[b * STAGE_FLOATS + (prs * 16 + pi) * XROW + pj] = 0.0f;
    }

    const int lane = tid & 31;
    const int warp = tid >> 5;
    const int g    = lane >> 2;
    const int t    = lane & 3;
    const int wm   = warp & 3;
    const int wn   = warp >> 2;
    const int rs   = wm >> 1;
    const int mcol = (wm & 1) * 64;
    const int nb   = wn * 64;

    // stage loader: stage s = kh*4 + icc, into buffer buf
    auto issue_stage = [&](int s, int buf) {
        const int kh  = s >> 2;
        const int icc = s & 3;
        const uint32_t base = smem_u + (uint32_t)(buf * STAGE_FLOATS * 4);
        // Xs: 1024 x 16B chunks
        #pragma unroll
        for (int it = 0; it < 4; ++it) {
            int idx = tid + it * 256;
            int prs = idx >> 9;
            int i   = (idx >> 5) & 15;
            int c   = idx & 31;
            int ih  = r0 + prs - kh;
            bool ok = (ih >= 0);
            int ihc = ok ? ih : 0;
            int ic  = icc * 16 + i;
            const float* gp = x + ((((nimg * CIN + ic) * HDIM + ihc) << 7) + c * 4);
            uint32_t sa = base + (uint32_t)(((prs * 16 + i) * XROW + 4 + c * 4) * 4);
            cp_async16(sa, gp, ok);
        }
        // Wf: 1536 x 16B chunks from contiguous per-stage region of g_wt
        const float* wsrc = g_wt + (kh * 4 + icc) * 6144;
        #pragma unroll
        for (int it = 0; it < 6; ++it) {
            int idx  = tid + it * 256;       // 0..1535
            int c    = idx & 3;
            int ln   = (idx >> 2) & 31;
            int wn2  = (idx >> 7) & 1;
            int ks   = (idx >> 8) & 1;
            int kw   = idx >> 9;
            const float* gp = wsrc + idx * 4;
            uint32_t sa = base + (uint32_t)((XS_FLOATS +
                          (((kw * 2 + ks) * 2 + wn2) * 32 + ln) * WROWF + c * 4) * 4);
            cp_async16(sa, gp, true);
        }
        asm volatile("cp.async.commit_group;\n");
    };

    float acc[4][8][4];
    #pragma unroll
    for (int mt = 0; mt < 4; ++mt)
        #pragma unroll
        for (int nt = 0; nt < 8; ++nt)
            #pragma unroll
            for (int q = 0; q < 4; ++q) acc[mt][nt][q] = 0.0f;

    issue_stage(0, 0);

    for (int s = 0; s < 12; ++s) {
        if (s + 1 < 12) {
            issue_stage(s + 1, (s + 1) & 1);
            asm volatile("cp.async.wait_group 1;\n");
        } else {
            asm volatile("cp.async.wait_group 0;\n");
        }
        __syncthreads();

        const float* Xs = smem + (s & 1) * STAGE_FLOATS + rs * 16 * XROW;
        const float* Wf = smem + (s & 1) * STAGE_FLOATS + XS_FLOATS;

        #pragma unroll
        for (int kw = 0; kw < 3; ++kw) {
            const int jb = mcol + 4 - kw + g;
            #pragma unroll
            for (int ks = 0; ks < 2; ++ks) {
                const int kr = ks * 8 + t;
                // B fragments: 4x LDS.128, conflict-free (20-float lane stride)
                const float4* wp4 = reinterpret_cast<const float4*>(
                    Wf + (((kw * 2 + ks) * 2 + wn) * 32 + lane) * WROWF);
                float4 q0 = wp4[0], q1 = wp4[1], q2 = wp4[2], q3 = wp4[3];
                float bf[16] = {q0.x, q0.y, q0.z, q0.w, q1.x, q1.y, q1.z, q1.w,
                                q2.x, q2.y, q2.z, q2.w, q3.x, q3.y, q3.z, q3.w};
                // A fragments (cvt.rna to tf32 after LDS)
                uint32_t a[4][4];
                #pragma unroll
                for (int mt = 0; mt < 4; ++mt) {
                    int jj = jb + mt * 16;
                    a[mt][0] = f2tf32(Xs[kr * XROW + jj]);
                    a[mt][1] = f2tf32(Xs[kr * XROW + jj + 8]);
                    a[mt][2] = f2tf32(Xs[(kr + 4) * XROW + jj]);
                    a[mt][3] = f2tf32(Xs[(kr + 4) * XROW + jj + 8]);
                }
                #pragma unroll
                for (int mt = 0; mt < 4; ++mt)
                    #pragma unroll
                    for (int nt = 0; nt < 8; ++nt)
                        mma_tf32(acc[mt][nt][0], acc[mt][nt][1], acc[mt][nt][2], acc[mt][nt][3],
                                 a[mt][0], a[mt][1], a[mt][2], a[mt][3],
                                 __float_as_uint(bf[2 * nt]), __float_as_uint(bf[2 * nt + 1]));
            }
        }
        __syncthreads();
    }

    // ---------------- Epilogue: bias + GELU + per-pixel GroupNorm ----------
    float b_r[16], ga[16], be[16];
    #pragma unroll
    for (int nt = 0; nt < 8; ++nt)
        #pragma unroll
        for (int j = 0; j < 2; ++j) {
            int q  = nt * 2 + j;
            int oc = nb + nt * 8 + 2 * t + j;
            b_r[q] = __ldg(bias + oc);
            ga[q]  = __ldg(gamma + oc);
            be[q]  = __ldg(beta + oc);
        }

    const int oh = r0 + rs;
    const long out_img = (long)nimg * COUT * HDIM * WDIM;

    #pragma unroll
    for (int mt = 0; mt < 4; ++mt) {
        #pragma unroll
        for (int h = 0; h < 2; ++h) {
            int ow = mcol + mt * 16 + g + 8 * h;
            float gv[16];
            #pragma unroll
            for (int nt = 0; nt < 8; ++nt)
                #pragma unroll
                for (int j = 0; j < 2; ++j) {
                    int q = nt * 2 + j;
                    float y = acc[mt][nt][2 * h + j] + b_r[q];
                    gv[q] = gelu_fast(y);
                }
            #pragma unroll
            for (int g2 = 0; g2 < 4; ++g2) {
                float s1 = gv[4 * g2] + gv[4 * g2 + 1] + gv[4 * g2 + 2] + gv[4 * g2 + 3];
                float s2 = gv[4 * g2] * gv[4 * g2] + gv[4 * g2 + 1] * gv[4 * g2 + 1] +
                           gv[4 * g2 + 2] * gv[4 * g2 + 2] + gv[4 * g2 + 3] * gv[4 * g2 + 3];
                s1 += __shfl_xor_sync(0xffffffffu, s1, 1);
                s2 += __shfl_xor_sync(0xffffffffu, s2, 1);
                s1 += __shfl_xor_sync(0xffffffffu, s1, 2);
                s2 += __shfl_xor_sync(0xffffffffu, s2, 2);
                float mean = s1 * (1.0f / 16.0f);
                float var  = s2 * (1.0f / 16.0f) - mean * mean;
                float rstd = rsqrtf(var + EPS);
                #pragma unroll
                for (int u = 0; u < 4; ++u) {
                    int q  = 4 * g2 + u;
                    int nt = q >> 1;
                    int j  = q & 1;
                    int oc = nb + nt * 8 + 2 * t + j;
                    float val = (gv[q] - mean) * rstd * ga[q] + be[q];
                    out[out_img + (long)oc * (HDIM * WDIM) + oh * WDIM + ow] = val;
                }
            }
        }
    }
}

// ---------------------------------------------------------------------------
// Launch
// ---------------------------------------------------------------------------
extern "C" void kernel_launch(void* const* d_in, const int* in_sizes, int n_in,
                              void* d_out, int out_size) {
    const float* x  = (const float*)d_in[0];
    const float* w  = (const float*)d_in[1];
    const float* b  = (const float*)d_in[2];
    const float* gw = (const float*)d_in[3];
    const float* gb = (const float*)d_in[4];
    float* out = (float*)d_out;

    wt_transform_kernel<<<(73728 + 255) / 256, 256>>>(w);

    cudaFuncSetAttribute(fused_kernel,
                         cudaFuncAttributeMaxDynamicSharedMemorySize, SMEM_BYTES);
    dim3 grid(HDIM / 2, NB);  // 64 x 32 = 2048 CTAs
    fused_kernel<<<grid, 256, SMEM_BYTES>>>(x, b, gw, gb, out);
}

// round 6
// speedup vs baseline: 1.0572x; 1.0572x over previous
#include <cuda_runtime.h>
#include <cstdint>

#define NB    32
#define CIN   64
#define COUT  128
#define HDIM  128
#define WDIM  128
#define EPS   1e-5f

// Fragment-ordered weights, tf32 bits:
// d = ((((s*3+kw)*4+ks)*2+wn)*32+lane)*16 + e,  s = kh*2 + hh (6 stages)
// e = nt*2+idx, lane = g*4+t
// value = w[ic = hh*32 + ks*8 + t + idx*4][oc = wn*64 + nt*8 + g][kh][kw]
__device__ float g_wt[73728];

__global__ void wt_transform_kernel(const float* __restrict__ w) {
    int d = blockIdx.x * blockDim.x + threadIdx.x;
    if (d >= 73728) return;
    int e    = d & 15;
    int lane = (d >> 4) & 31;
    int wn   = (d >> 9) & 1;
    int ks   = (d >> 10) & 3;
    int r    = d >> 12;          // 0..17
    int kw   = r % 3;
    int s    = r / 3;            // 0..5
    int kh   = s >> 1;
    int hh   = s & 1;
    int nt   = e >> 1;
    int idx  = e & 1;
    int g    = lane >> 2;
    int t    = lane & 3;
    int ic   = hh * 32 + ks * 8 + t + idx * 4;
    int oc   = wn * 64 + nt * 8 + g;
    float v = w[((ic * COUT + oc) * 3 + kh) * 3 + kw];
    uint32_t rb;
    asm("cvt.rna.tf32.f32 %0, %1;" : "=r"(rb) : "f"(v));
    g_wt[d] = __uint_as_float(rb);
}

// ---------------------------------------------------------------------------
// Helpers
// ---------------------------------------------------------------------------
__device__ __forceinline__ uint32_t f2tf32(float f) {
    uint32_t r;
    asm("cvt.rna.tf32.f32 %0, %1;" : "=r"(r) : "f"(f));
    return r;
}
__device__ __forceinline__ void cp_async16(uint32_t saddr, const void* gaddr) {
    asm volatile("cp.async.cg.shared.global [%0], [%1], 16;\n" :: "r"(saddr), "l"(gaddr));
}
__device__ __forceinline__ void sts128(uint32_t saddr, uint32_t v0, uint32_t v1,
                                       uint32_t v2, uint32_t v3) {
    asm volatile("st.shared.v4.b32 [%0], {%1,%2,%3,%4};"
                 :: "r"(saddr), "r"(v0), "r"(v1), "r"(v2), "r"(v3));
}
// Zero-MUFU tanh-GELU (validated R3/R4: rel_err unchanged vs __expf version)
__device__ __forceinline__ float gelu_fast(float y) {
    float y2 = y * y;
    float v  = y * fmaf(-0.10294832f, y2, -2.3022083f);
    v = fminf(fmaxf(v, -126.0f), 126.0f);
    float r = v + 12582912.0f;
    float f = v - (r - 12582912.0f);
    int  ri = __float_as_int(r);
    float p = fmaf(f, 0.0096181291f, 0.0555041087f);
    p = fmaf(f, p, 0.2402265069f);
    p = fmaf(f, p, 0.6931471806f);
    p = fmaf(f, p, 1.0f);
    float w = __int_as_float(__float_as_int(p) + (ri << 23));
    float s = 1.0f + w;
    float x = __int_as_float(0x7EF311C3u - (uint32_t)__float_as_int(s));
    x = x * (2.0f - s * x);
    x = x * (2.0f - s * x);
    return y * x;
}
__device__ __forceinline__ void mma_tf32(float& d0, float& d1, float& d2, float& d3,
                                         uint32_t a0, uint32_t a1, uint32_t a2, uint32_t a3,
                                         uint32_t b0, uint32_t b1) {
    asm volatile(
        "mma.sync.aligned.m16n8k8.row.col.f32.tf32.tf32.f32 "
        "{%0,%1,%2,%3}, {%4,%5,%6,%7}, {%8,%9}, {%0,%1,%2,%3};\n"
        : "+f"(d0), "+f"(d1), "+f"(d2), "+f"(d3)
        : "r"(a0), "r"(a1), "r"(a2), "r"(a3), "r"(b0), "r"(b1));
}

// SMEM layout per buffer (floats):
//   Xs: 2 pixel-row-sets x 32 ic x 136  (tf32 bits; data at j=4..131, zeros j=0..3)
//   Wf: [kw3][ks4][wn2][lane32][20]     (16 data + 4 pad)
#define XROW         136
#define XS_FLOATS    (2 * 32 * XROW)            // 8704
#define WROWF        20
#define WS_FLOATS    (3 * 4 * 2 * 32 * WROWF)   // 15360
#define STAGE_FLOATS (XS_FLOATS + WS_FLOATS)    // 24064
#define STAGE_BYTES  (STAGE_FLOATS * 4)         // 96256
#define SMEM_BYTES   (2 * STAGE_BYTES)          // 192512

// ---------------------------------------------------------------------------
// Fused kernel: CTA = 2 pixel rows (M=256) x 128 oc, 16 warps (8m x 2n),
// warp tile 32x64, 6 double-buffered stages of K=96 (kh x 32-ic half).
// ---------------------------------------------------------------------------
__global__ void __launch_bounds__(512, 1)
fused_kernel(const float* __restrict__ x,
             const float* __restrict__ bias,
             const float* __restrict__ gamma,
             const float* __restrict__ beta,
             float* __restrict__ out) {
    extern __shared__ float smf[];
    const uint32_t smem_u = (uint32_t)__cvta_generic_to_shared(smf);
    const int tid  = threadIdx.x;
    const int nimg = blockIdx.y;
    const int r0   = blockIdx.x * 2;

    const int lane = tid & 31;
    const int warp = tid >> 5;
    const int g    = lane >> 2;
    const int t    = lane & 3;
    const int wm   = warp & 7;     // 8 m-warps
    const int wn   = warp >> 3;    // 2 n-warps
    const int rs   = wm >> 2;      // pixel row within CTA
    const int mcol = (wm & 3) * 32;
    const int nb   = wn * 64;

    // Zero left-pad cols j=0..3 of Xs rows in both buffers (512 writes, 1/thread)
    {
        int b   = tid >> 8;
        int row = (tid >> 2) & 63;
        int j   = tid & 3;
        smf[b * STAGE_FLOATS + row * XROW + j] = 0.0f;
    }

    // ---------------- Producer helpers (inline) ----------------
    // X chunk mapping: c in 0..2047 (float4 units): prs=c>>10, i=(c>>5)&31, cc=c&31
    // W chunk mapping: c in 0..3071 (16B units):  row=c>>2, part=c&3

    // Prologue: produce stage 0 (kh=0, hh=0) into buffer 0
    {
        #pragma unroll
        for (int k = 0; k < 4; ++k) {
            int c   = tid + k * 512;
            int prs = c >> 10;
            int i   = (c >> 5) & 31;
            int cc  = c & 31;
            int ih  = r0 + prs;  // kh=0 -> always >= 0
            float4 v = __ldg((const float4*)(x +
                       ((((size_t)(nimg * CIN + i) * HDIM + ih)) << 7) + cc * 4));
            uint32_t sa = smem_u + (uint32_t)(((prs * 32 + i) * XROW + 4 + cc * 4) * 4);
            sts128(sa, f2tf32(v.x), f2tf32(v.y), f2tf32(v.z), f2tf32(v.w));
        }
        const float* wsrc = g_wt;  // stage 0
        #pragma unroll
        for (int k = 0; k < 6; ++k) {
            int c    = tid + k * 512;
            int row  = c >> 2;
            int part = c & 3;
            uint32_t sa = smem_u + (uint32_t)((XS_FLOATS + row * WROWF + part * 4) * 4);
            cp_async16(sa, wsrc + c * 4);
        }
        asm volatile("cp.async.commit_group;\n");
        asm volatile("cp.async.wait_group 0;\n");
    }
    __syncthreads();

    float acc[2][8][4];
    #pragma unroll
    for (int mt = 0; mt < 2; ++mt)
        #pragma unroll
        for (int nt = 0; nt < 8; ++nt)
            #pragma unroll
            for (int q = 0; q < 4; ++q) acc[mt][nt][q] = 0.0f;

    #pragma unroll 1
    for (int s = 0; s < 6; ++s) {
        const int  buf  = s & 1;
        const bool have = (s < 5);
        float4 xr[4];

        if (have) {
            const int kh1 = (s + 1) >> 1;
            const int hh1 = (s + 1) & 1;
            // Prefetch X for s+1 into registers (latency hidden under MMA)
            #pragma unroll
            for (int k = 0; k < 4; ++k) {
                int c   = tid + k * 512;
                int prs = c >> 10;
                int i   = (c >> 5) & 31;
                int cc  = c & 31;
                int ih  = r0 + prs - kh1;
                if (ih >= 0) {
                    xr[k] = __ldg((const float4*)(x +
                            ((((size_t)(nimg * CIN + hh1 * 32 + i) * HDIM + ih)) << 7) + cc * 4));
                } else {
                    xr[k] = make_float4(0.f, 0.f, 0.f, 0.f);
                }
            }
            // Weights for s+1 via cp.async (overlaps with MMA below)
            const float* wsrc = g_wt + (size_t)(s + 1) * 12288;
            const uint32_t wb = smem_u + (uint32_t)((buf ^ 1) * STAGE_BYTES + XS_FLOATS * 4);
            #pragma unroll
            for (int k = 0; k < 6; ++k) {
                int c    = tid + k * 512;
                int row  = c >> 2;
                int part = c & 3;
                cp_async16(wb + (uint32_t)((row * WROWF + part * 4) * 4), wsrc + c * 4);
            }
            asm volatile("cp.async.commit_group;\n");
        }

        // ---------------- MMA phase on buffer buf ----------------
        const float* Xb = smf + buf * STAGE_FLOATS + rs * 32 * XROW;
        const float* Wf = smf + buf * STAGE_FLOATS + XS_FLOATS;

        #pragma unroll
        for (int kw = 0; kw < 3; ++kw) {
            const int jb = mcol + 4 - kw + g;
            #pragma unroll
            for (int ks = 0; ks < 4; ++ks) {
                const float4* wp = (const float4*)(Wf +
                    (size_t)(((kw * 4 + ks) * 2 + wn) * 32 + lane) * WROWF);
                float4 q0 = wp[0], q1 = wp[1], q2 = wp[2], q3 = wp[3];
                const int kr = ks * 8 + t;
                uint32_t a[2][4];
                #pragma unroll
                for (int mt = 0; mt < 2; ++mt) {
                    int jj = jb + mt * 16;
                    a[mt][0] = __float_as_uint(Xb[kr * XROW + jj]);
                    a[mt][1] = __float_as_uint(Xb[kr * XROW + jj + 8]);
                    a[mt][2] = __float_as_uint(Xb[(kr + 4) * XROW + jj]);
                    a[mt][3] = __float_as_uint(Xb[(kr + 4) * XROW + jj + 8]);
                }
                float bf[16] = {q0.x, q0.y, q0.z, q0.w, q1.x, q1.y, q1.z, q1.w,
                                q2.x, q2.y, q2.z, q2.w, q3.x, q3.y, q3.z, q3.w};
                #pragma unroll
                for (int mt = 0; mt < 2; ++mt)
                    #pragma unroll
                    for (int nt = 0; nt < 8; ++nt)
                        mma_tf32(acc[mt][nt][0], acc[mt][nt][1], acc[mt][nt][2], acc[mt][nt][3],
                                 a[mt][0], a[mt][1], a[mt][2], a[mt][3],
                                 __float_as_uint(bf[2 * nt]), __float_as_uint(bf[2 * nt + 1]));
            }
        }

        if (have) {
            // Store prefetched X (tf32-converted) into the next buffer
            const uint32_t xb = smem_u + (uint32_t)((buf ^ 1) * STAGE_BYTES);
            #pragma unroll
            for (int k = 0; k < 4; ++k) {
                int c   = tid + k * 512;
                int prs = c >> 10;
                int i   = (c >> 5) & 31;
                int cc  = c & 31;
                uint32_t sa = xb + (uint32_t)(((prs * 32 + i) * XROW + 4 + cc * 4) * 4);
                sts128(sa, f2tf32(xr[k].x), f2tf32(xr[k].y), f2tf32(xr[k].z), f2tf32(xr[k].w));
            }
            asm volatile("cp.async.wait_group 0;\n");
        }
        __syncthreads();
    }

    // ---------------- Epilogue: bias + GELU + per-pixel GroupNorm ----------
    float b_r[16];
    #pragma unroll
    for (int nt = 0; nt < 8; ++nt)
        #pragma unroll
        for (int j = 0; j < 2; ++j)
            b_r[nt * 2 + j] = __ldg(bias + nb + nt * 8 + 2 * t + j);

    const int oh = r0 + rs;
    const size_t out_img = (size_t)nimg * COUT * HDIM * WDIM;

    #pragma unroll
    for (int mt = 0; mt < 2; ++mt) {
        #pragma unroll
        for (int h = 0; h < 2; ++h) {
            int ow = mcol + mt * 16 + g + 8 * h;
            float gv[16];
            #pragma unroll
            for (int nt = 0; nt < 8; ++nt)
                #pragma unroll
                for (int j = 0; j < 2; ++j) {
                    int q = nt * 2 + j;
                    gv[q] = gelu_fast(acc[mt][nt][2 * h + j] + b_r[q]);
                }
            // Groups of 16 channels live in one lane-quad: 2 shfl pairs
            #pragma unroll
            for (int g2 = 0; g2 < 4; ++g2) {
                float s1 = gv[4 * g2] + gv[4 * g2 + 1] + gv[4 * g2 + 2] + gv[4 * g2 + 3];
                float s2 = fmaf(gv[4 * g2], gv[4 * g2],
                           fmaf(gv[4 * g2 + 1], gv[4 * g2 + 1],
                           fmaf(gv[4 * g2 + 2], gv[4 * g2 + 2],
                                gv[4 * g2 + 3] * gv[4 * g2 + 3])));
                s1 += __shfl_xor_sync(0xffffffffu, s1, 1);
                s2 += __shfl_xor_sync(0xffffffffu, s2, 1);
                s1 += __shfl_xor_sync(0xffffffffu, s1, 2);
                s2 += __shfl_xor_sync(0xffffffffu, s2, 2);
                float mean = s1 * (1.0f / 16.0f);
                float var  = fmaf(s2, 1.0f / 16.0f, -mean * mean);
                float rstd = rsqrtf(var + EPS);
                #pragma unroll
                for (int u = 0; u < 4; ++u) {
                    int q  = 4 * g2 + u;
                    int nt = q >> 1;
                    int j  = q & 1;
                    int oc = nb + nt * 8 + 2 * t + j;
                    float val = fmaf((gv[q] - mean) * rstd, __ldg(gamma + oc), __ldg(beta + oc));
                    out[out_img + (size_t)oc * (HDIM * WDIM) + oh * WDIM + ow] = val;
                }
            }
        }
    }
}

// ---------------------------------------------------------------------------
// Launch
// ---------------------------------------------------------------------------
extern "C" void kernel_launch(void* const* d_in, const int* in_sizes, int n_in,
                              void* d_out, int out_size) {
    const float* x  = (const float*)d_in[0];
    const float* w  = (const float*)d_in[1];
    const float* b  = (const float*)d_in[2];
    const float* gw = (const float*)d_in[3];
    const float* gb = (const float*)d_in[4];
    float* out = (float*)d_out;

    wt_transform_kernel<<<(73728 + 255) / 256, 256>>>(w);

    cudaFuncSetAttribute(fused_kernel,
                         cudaFuncAttributeMaxDynamicSharedMemorySize, SMEM_BYTES);
    dim3 grid(HDIM / 2, NB);  // 64 x 32 = 2048 CTAs
    fused_kernel<<<grid, 512, SMEM_BYTES>>>(x, b, gw, gb, out);
}